// round 5
// baseline (speedup 1.0000x reference)
#include <cuda_runtime.h>
#include <cuda_bf16.h>
#include <cstdint>
#include <math.h>

#define HID 128
#define NMAX 50000
#define NPAD 50048          // 391*128, covers last tile
#define EMAX 600000
#define IMG_ROW 512         // image row: 256B hi || 256B lo
#define SM_ROW 144          // smem row stride (conflict-free for ldmatrix)
#define SM_IMG 18432        // 128*144
#define SM_BUF 73728        // 4 regions (Ahi,Alo,Bhi,Blo)
#define SMEM_TOTAL 147456   // double buffered

// ---------------- scratch (device globals) ----------------------------------
__device__ float g_q [NMAX * HID];
__device__ float g_k [NMAX * HID];
__device__ float g_v [NMAX * HID];
__device__ float g_g [NMAX * HID];
__device__ float g_hc[NMAX * HID];
__device__ __align__(16) unsigned char g_ipred[(size_t)NPAD * IMG_ROW];
__device__ __align__(16) unsigned char g_iprev[(size_t)NPAD * IMG_ROW];
__device__ __align__(16) unsigned char g_iy  [(size_t)NPAD * IMG_ROW];
__device__ __align__(16) unsigned char g_it1 [(size_t)NPAD * IMG_ROW];
__device__ __align__(16) unsigned char g_it2 [(size_t)NPAD * IMG_ROW];
__device__ __align__(16) unsigned char g_ihc [(size_t)NPAD * IMG_ROW];
__device__ __align__(16) unsigned char g_wpre[10 * 65536];   // 10 weight chunks
__device__ int g_cnt[NMAX];
__device__ int g_linc[NMAX];
__device__ int g_bsum[256];
__device__ int g_bofs[256];
__device__ int g_start[NMAX];
__device__ int g_cur[NMAX];
__device__ int g_ccol[EMAX];

// ---------------- helpers ----------------------------------------------------
__device__ __forceinline__ uint32_t smem_u32(const void* p) {
    uint32_t a;
    asm("{ .reg .u64 t; cvta.to.shared.u64 t, %1; cvt.u32.u64 %0, t; }" : "=r"(a) : "l"(p));
    return a;
}
__device__ __forceinline__ uint32_t pk(float a, float b) {
    __nv_bfloat162 t = __floats2bfloat162_rn(a, b);
    return *reinterpret_cast<uint32_t*>(&t);
}
__device__ __forceinline__ float bf16r(float x) {
    return __bfloat162float(__float2bfloat16(x));
}
__device__ __forceinline__ void ldsm4(uint32_t& r0, uint32_t& r1, uint32_t& r2, uint32_t& r3,
                                      uint32_t addr) {
    asm volatile("ldmatrix.sync.aligned.m8n8.x4.shared.b16 {%0,%1,%2,%3}, [%4];"
                 : "=r"(r0), "=r"(r1), "=r"(r2), "=r"(r3) : "r"(addr));
}
__device__ __forceinline__ void mma16816(float* d, const uint32_t* a, uint32_t b0, uint32_t b1) {
    asm volatile(
        "mma.sync.aligned.m16n8k16.row.col.f32.bf16.bf16.f32 "
        "{%0,%1,%2,%3}, {%4,%5,%6,%7}, {%8,%9}, {%0,%1,%2,%3};"
        : "+f"(d[0]), "+f"(d[1]), "+f"(d[2]), "+f"(d[3])
        : "r"(a[0]), "r"(a[1]), "r"(a[2]), "r"(a[3]), "r"(b0), "r"(b1));
}
__device__ __forceinline__ void cp16(uint32_t saddr, const void* gaddr) {
    asm volatile("cp.async.cg.shared.global [%0], [%1], 16;" :: "r"(saddr), "l"(gaddr));
}

// ---------------- input convert: fp32 -> hi/lo image ------------------------
__global__ void hconv_kernel(const float* __restrict__ hp, const float* __restrict__ hv,
                             unsigned char* __restrict__ ip, unsigned char* __restrict__ iv,
                             int n) {
    int idx = blockIdx.x * blockDim.x + threadIdx.x;
    if (idx >= n * 32) return;
    const float* src = blockIdx.y ? hv : hp;
    unsigned char* dst = blockIdx.y ? iv : ip;
    int row = idx >> 5, sg = idx & 31;
    float4 a = *(const float4*)&src[row * 128 + sg * 4];
    float hx = bf16r(a.x), hy = bf16r(a.y), hz = bf16r(a.z), hw = bf16r(a.w);
    unsigned char* r = dst + (size_t)row * IMG_ROW + sg * 8;
    *(uint2*)(r)       = make_uint2(pk(hx, hy), pk(hz, hw));
    *(uint2*)(r + 256) = make_uint2(pk(a.x - hx, a.y - hy), pk(a.z - hz, a.w - hw));
}

// ---------------- weight convert: all 10 chunks in one launch ----------------
struct WArg { const float* W[10]; };
__global__ void wconv_kernel(WArg a, unsigned char* __restrict__ dst) {
    int slot = blockIdx.y;
    int idx = blockIdx.x * blockDim.x + threadIdx.x;   // 0..8191
    int n = idx & 127, kp = idx >> 7;                  // kp 0..63
    int kof = (slot == 7 || slot == 9) ? 128 : 0;
    const float* W = a.W[slot];
    int k = kof + kp * 2;
    float w0 = W[k * 128 + n], w1 = W[(k + 1) * 128 + n];
    float h0 = bf16r(w0), h1 = bf16r(w1);
    unsigned char* base = dst + slot * 65536 + n * IMG_ROW + kp * 4;
    *(uint32_t*)(base)       = pk(h0, h1);
    *(uint32_t*)(base + 256) = pk(w0 - h0, w1 - h1);
}

// ---------------- CSR build --------------------------------------------------
__global__ void zero_int_kernel(int* __restrict__ p, int n) {
    int i = blockIdx.x * blockDim.x + threadIdx.x;
    if (i < n) p[i] = 0;
}
__global__ void hist_kernel(const int* __restrict__ rows, int* __restrict__ cnt, int E) {
    int e = blockIdx.x * blockDim.x + threadIdx.x;
    if (e < E) atomicAdd(&cnt[rows[e]], 1);
}
__device__ __forceinline__ int wscan_incl(int x, int lane) {
    #pragma unroll
    for (int o = 1; o < 32; o <<= 1) {
        int t = __shfl_up_sync(0xffffffffu, x, o);
        if (lane >= o) x += t;
    }
    return x;
}
__device__ __forceinline__ int bscan256(int v, int* ws, int tid) {
    int lane = tid & 31, w = tid >> 5;
    int x = wscan_incl(v, lane);
    if (lane == 31) ws[w] = x;
    __syncthreads();
    if (tid < 8) {
        int s = ws[tid];
        #pragma unroll
        for (int o = 1; o < 8; o <<= 1) {
            int t = __shfl_up_sync(0xffu, s, o);
            if (tid >= o) s += t;
        }
        ws[tid] = s;
    }
    __syncthreads();
    return x + (w ? ws[w - 1] : 0);
}
__global__ __launch_bounds__(256) void scan1_kernel(const int* __restrict__ cnt,
                                                    int* __restrict__ linc,
                                                    int* __restrict__ bsum, int n) {
    __shared__ int ws[8];
    int tid = threadIdx.x, i = blockIdx.x * 256 + tid;
    int v = (i < n) ? cnt[i] : 0;
    int incl = bscan256(v, ws, tid);
    if (i < n) linc[i] = incl;
    if (tid == 255) bsum[blockIdx.x] = incl;
}
__global__ __launch_bounds__(256) void scan2_kernel(const int* __restrict__ bsum,
                                                    int* __restrict__ bofs, int nb) {
    __shared__ int ws[8];
    int tid = threadIdx.x;
    int v = (tid < nb) ? bsum[tid] : 0;
    int incl = bscan256(v, ws, tid);
    if (tid < nb) bofs[tid] = incl - v;   // exclusive
}
__global__ void scan3_kernel(const int* __restrict__ bofs, const int* __restrict__ linc,
                             const int* __restrict__ cnt, int* __restrict__ start,
                             int* __restrict__ cur, int n) {
    int i = blockIdx.x * 256 + threadIdx.x;
    if (i < n) {
        int s = bofs[blockIdx.x] + linc[i] - cnt[i];
        start[i] = s;
        cur[i] = s;
    }
}
__global__ void scatter_kernel(const int* __restrict__ rows, const int* __restrict__ cols,
                               int* __restrict__ cur, int* __restrict__ ccol, int E) {
    int e = blockIdx.x * blockDim.x + threadIdx.x;
    if (e < E) {
        int r = rows[e];
        int p = atomicAdd(&cur[r], 1);
        ccol[p] = cols[e];
    }
}

// ---------------- fused sparse attention (one warp per node) -----------------
// reads q,k,v fp32; writes y as hi/lo bf16 image (GEMM input for Wo)
__global__ __launch_bounds__(256) void attn_kernel(
    const float* __restrict__ q, const float* __restrict__ k, const float* __restrict__ v,
    const int* __restrict__ ccol, const int* __restrict__ start, const int* __restrict__ cnt,
    unsigned char* __restrict__ yimg, int N)
{
    int warp = (blockIdx.x * blockDim.x + threadIdx.x) >> 5;
    int lane = threadIdx.x & 31;
    if (warp >= N) return;
    int node = warp;
    int s = start[node], e = s + cnt[node];

    const float4* q4 = (const float4*)q;
    const float4* k4 = (const float4*)k;
    const float4* v4 = (const float4*)v;

    float4 qv = q4[node * 32 + lane];

    float mx_x = -INFINITY, mx_y = -INFINITY, mx_z = -INFINITY, mx_w = -INFINITY;
    float l_x = 0.f, l_y = 0.f, l_z = 0.f, l_w = 0.f;
    float4 acc = make_float4(0.f, 0.f, 0.f, 0.f);

    for (int j = s; j < e; j++) {
        int c = __ldg(&ccol[j]);
        float4 kv = k4[c * 32 + lane];
        float sx = qv.x * kv.x;
        float sy = qv.y * kv.y;
        float sz = qv.z * kv.z;
        float sw = qv.w * kv.w;
        #pragma unroll
        for (int o = 16; o > 0; o >>= 1) {
            sx += __shfl_xor_sync(0xffffffffu, sx, o);
            sy += __shfl_xor_sync(0xffffffffu, sy, o);
            sz += __shfl_xor_sync(0xffffffffu, sz, o);
            sw += __shfl_xor_sync(0xffffffffu, sw, o);
        }
        float4 vv = v4[c * 32 + lane];
        if (sx > mx_x || sy > mx_y || sz > mx_z || sw > mx_w) {
            float nx = fmaxf(mx_x, sx), ny = fmaxf(mx_y, sy);
            float nz = fmaxf(mx_z, sz), nw = fmaxf(mx_w, sw);
            float cx = __expf(mx_x - nx), cy = __expf(mx_y - ny);
            float cz = __expf(mx_z - nz), cw = __expf(mx_w - nw);
            l_x *= cx; l_y *= cy; l_z *= cz; l_w *= cw;
            acc.x *= cx; acc.y *= cy; acc.z *= cz; acc.w *= cw;
            mx_x = nx; mx_y = ny; mx_z = nz; mx_w = nw;
        }
        float px = __expf(sx - mx_x), py = __expf(sy - mx_y);
        float pz = __expf(sz - mx_z), pw = __expf(sw - mx_w);
        l_x += px; l_y += py; l_z += pz; l_w += pw;
        acc.x += px * vv.x; acc.y += py * vv.y;
        acc.z += pz * vv.z; acc.w += pw * vv.w;
    }
    float ox = acc.x * (l_x > 0.f ? 1.f / l_x : 0.f);
    float oy = acc.y * (l_y > 0.f ? 1.f / l_y : 0.f);
    float oz = acc.z * (l_z > 0.f ? 1.f / l_z : 0.f);
    float ow = acc.w * (l_w > 0.f ? 1.f / l_w : 0.f);
    float hx = bf16r(ox), hy = bf16r(oy), hz = bf16r(oz), hw = bf16r(ow);
    unsigned char* yr = yimg + (size_t)node * IMG_ROW + lane * 8;
    *(uint2*)(yr)       = make_uint2(pk(hx, hy), pk(hz, hw));
    *(uint2*)(yr + 256) = make_uint2(pk(ox - hx, oy - hy), pk(oz - hz, ow - hw));
}

// ---------------- pipelined HMMA bf16-split GEMM -----------------------------
// A,B are hi/lo images (IMG_ROW 512B rows). K = nchunk*128, 2 substages/chunk.
// EPI: 1 *scale | 2 silu | 3 sigmoid | 4 C=P2+P1*val | 5 C=val+P1
// WF: write fp32 Cf, WI: write hi/lo image Cimg
__device__ __forceinline__ void stage_cp(uint32_t sbuf, const unsigned char* Aimg,
                                         const unsigned char* Bc, int h, int tid, int bm) {
    #pragma unroll
    for (int i = 0; i < 16; i++) {
        int t = tid + i * 256;
        int region = t >> 10, row = (t >> 3) & 127, sg = t & 7;
        int lo = (region & 1) * 256;
        const unsigned char* g = (region < 2)
            ? Aimg + (size_t)(bm + row) * IMG_ROW + lo + h * 128 + sg * 16
            : Bc   + row * IMG_ROW + lo + h * 128 + sg * 16;
        cp16(sbuf + region * SM_IMG + row * SM_ROW + sg * 16, g);
    }
    asm volatile("cp.async.commit_group;" ::: "memory");
}

template<int EPI, int WF, int WI>
__device__ __forceinline__ void gemm_body(
    const unsigned char* __restrict__ A1, const unsigned char* __restrict__ A2,
    const unsigned char* __restrict__ B, const float* __restrict__ bias,
    const float* __restrict__ P1, const float* __restrict__ P2,
    float* __restrict__ Cf, unsigned char* __restrict__ Cimg,
    int M, int nchunk, float scale, char* smem, int bm)
{
    const uint32_t sb = smem_u32(smem);
    const int tid = threadIdx.x, wid = tid >> 5, lane = tid & 31;
    const int wm = (wid & 3) * 32, wn = (wid >> 2) * 64;
    const int S = nchunk * 2;

    float acc[2][8][4];
    #pragma unroll
    for (int mt = 0; mt < 2; mt++)
        #pragma unroll
        for (int nt = 0; nt < 8; nt++)
            #pragma unroll
            for (int r = 0; r < 4; r++) acc[mt][nt][r] = 0.f;

    stage_cp(sb, A1, B, 0, tid, bm);
    {
        const unsigned char* Ai = (S > 2 && 1 >= 2) ? A2 : A1;  // s=1 -> chunk0
        stage_cp(sb + SM_BUF, Ai, B, 1, tid, bm);
    }

    const int lrow = lane & 15, lc16 = (lane >> 4) * 16;

    for (int s = 0; s < S; s++) {
        if (s + 1 < S) asm volatile("cp.async.wait_group 1;" ::: "memory");
        else           asm volatile("cp.async.wait_group 0;" ::: "memory");
        __syncthreads();
        const uint32_t base = sb + (s & 1) * SM_BUF;
        #pragma unroll
        for (int ks = 0; ks < 4; ks++) {
            const uint32_t kb = (uint32_t)(ks * 32);
            uint32_t ah[2][4], al[2][4], bh[8][2], bl[8][2];
            #pragma unroll
            for (int mt = 0; mt < 2; mt++) {
                uint32_t ad = base + (wm + mt * 16 + lrow) * SM_ROW + lc16 + kb;
                ldsm4(ah[mt][0], ah[mt][1], ah[mt][2], ah[mt][3], ad);
                ldsm4(al[mt][0], al[mt][1], al[mt][2], al[mt][3], ad + SM_IMG);
            }
            #pragma unroll
            for (int j = 0; j < 4; j++) {
                uint32_t bd = base + 2 * SM_IMG + (wn + j * 16 + lrow) * SM_ROW + lc16 + kb;
                uint32_t r0, r1, r2, r3;
                ldsm4(r0, r1, r2, r3, bd);
                bh[2*j][0] = r0; bh[2*j+1][0] = r1; bh[2*j][1] = r2; bh[2*j+1][1] = r3;
                ldsm4(r0, r1, r2, r3, bd + SM_IMG);
                bl[2*j][0] = r0; bl[2*j+1][0] = r1; bl[2*j][1] = r2; bl[2*j+1][1] = r3;
            }
            #pragma unroll
            for (int mt = 0; mt < 2; mt++)
                #pragma unroll
                for (int nt = 0; nt < 8; nt++) {
                    mma16816(acc[mt][nt], ah[mt], bh[nt][0], bh[nt][1]);
                    mma16816(acc[mt][nt], ah[mt], bl[nt][0], bl[nt][1]);
                    mma16816(acc[mt][nt], al[mt], bh[nt][0], bh[nt][1]);
                }
        }
        __syncthreads();
        if (s + 2 < S) {
            int ns = s + 2;
            const unsigned char* Ai = (ns >= 2) ? A2 : A1;
            stage_cp(sb + (s & 1) * SM_BUF, Ai, B + (ns >> 1) * 65536, ns & 1, tid, bm);
        }
    }

    // epilogue from register accumulators
    #pragma unroll
    for (int mt = 0; mt < 2; mt++) {
        #pragma unroll
        for (int half = 0; half < 2; half++) {
            int row = bm + wm + mt * 16 + (lane >> 2) + half * 8;
            if (row < M) {
                #pragma unroll
                for (int nt = 0; nt < 8; nt++) {
                    int col = wn + nt * 8 + 2 * (lane & 3);
                    float2 bs = *(const float2*)&bias[col];
                    float v0 = acc[mt][nt][half * 2 + 0] + bs.x;
                    float v1 = acc[mt][nt][half * 2 + 1] + bs.y;
                    if (EPI == 1) { v0 *= scale; v1 *= scale; }
                    if (EPI == 2) { v0 = v0 / (1.f + __expf(-v0)); v1 = v1 / (1.f + __expf(-v1)); }
                    if (EPI == 3) { v0 = 1.f / (1.f + __expf(-v0)); v1 = 1.f / (1.f + __expf(-v1)); }
                    int idx = row * 128 + col;
                    if (EPI == 4) {
                        float2 gm = *(const float2*)&P1[idx];
                        float2 hp = *(const float2*)&P2[idx];
                        v0 = hp.x + gm.x * v0;
                        v1 = hp.y + gm.y * v1;
                    } else if (EPI == 5) {
                        float2 ad = *(const float2*)&P1[idx];
                        v0 += ad.x; v1 += ad.y;
                    }
                    if (WF) *(float2*)&Cf[idx] = make_float2(v0, v1);
                    if (WI) {
                        float h0 = bf16r(v0), h1 = bf16r(v1);
                        unsigned char* r = Cimg + (size_t)row * IMG_ROW + col * 2;
                        *(uint32_t*)(r)       = pk(h0, h1);
                        *(uint32_t*)(r + 256) = pk(v0 - h0, v1 - h1);
                    }
                }
            }
        }
    }
}

template<int EPI, int WF, int WI>
__global__ __launch_bounds__(256, 1) void tgemm(
    const unsigned char* __restrict__ A1, const unsigned char* __restrict__ A2,
    const unsigned char* __restrict__ B, const float* __restrict__ bias,
    const float* __restrict__ P1, const float* __restrict__ P2,
    float* __restrict__ Cf, unsigned char* __restrict__ Cimg,
    int M, int nchunk, float scale)
{
    extern __shared__ char smem[];
    gemm_body<EPI, WF, WI>(A1, A2, B, bias, P1, P2, Cf, Cimg, M, nchunk, scale,
                           smem, blockIdx.x * 128);
}

__global__ __launch_bounds__(256, 1) void qkv_kernel(
    const unsigned char* __restrict__ ipred, const unsigned char* __restrict__ iprev,
    const unsigned char* __restrict__ wpre,
    const float* __restrict__ bq, const float* __restrict__ bk, const float* __restrict__ bv,
    float* __restrict__ q, float* __restrict__ k, float* __restrict__ v,
    int M, float qs)
{
    extern __shared__ char smem[];
    int y = blockIdx.y;
    const unsigned char* A = (y == 1) ? iprev : ipred;
    const unsigned char* B = wpre + y * 65536;
    const float* bias = (y == 0) ? bq : (y == 1) ? bk : bv;
    float* C = (y == 0) ? q : (y == 1) ? k : v;
    float sc = (y == 0) ? qs : 1.f;
    gemm_body<1, 1, 0>(A, nullptr, B, bias, nullptr, nullptr, C, nullptr, M, 1, sc,
                       smem, blockIdx.x * 128);
}

// ---------------- launch -----------------------------------------------------
extern "C" void kernel_launch(void* const* d_in, const int* in_sizes, int n_in,
                              void* d_out, int out_size) {
    const float* h_prev = (const float*)d_in[0];
    const float* h_pred = (const float*)d_in[1];
    const float* Wq  = (const float*)d_in[2];  const float* bq  = (const float*)d_in[3];
    const float* Wk  = (const float*)d_in[4];  const float* bk  = (const float*)d_in[5];
    const float* Wv  = (const float*)d_in[6];  const float* bv  = (const float*)d_in[7];
    const float* Wo  = (const float*)d_in[8];  const float* bo  = (const float*)d_in[9];
    const float* Wg1 = (const float*)d_in[10]; const float* bg1 = (const float*)d_in[11];
    const float* Wg2 = (const float*)d_in[12]; const float* bg2 = (const float*)d_in[13];
    const float* Wm1 = (const float*)d_in[14]; const float* bm1 = (const float*)d_in[15];
    const float* Wm2 = (const float*)d_in[16]; const float* bm2 = (const float*)d_in[17];
    const int* rows  = (const int*)d_in[18];
    const int* cols  = (const int*)d_in[19];
    const int N = in_sizes[0] / HID;
    const int E = in_sizes[18];
    float* out = (float*)d_out;

    float *q, *k, *v, *g, *hc;
    int *cnt, *linc, *bsum, *bofs, *start, *cur, *ccol;
    unsigned char *ipred, *iprev, *iy, *it1, *it2, *ihc, *wpre;
    cudaGetSymbolAddress((void**)&q,   g_q);
    cudaGetSymbolAddress((void**)&k,   g_k);
    cudaGetSymbolAddress((void**)&v,   g_v);
    cudaGetSymbolAddress((void**)&g,   g_g);
    cudaGetSymbolAddress((void**)&hc,  g_hc);
    cudaGetSymbolAddress((void**)&ipred, g_ipred);
    cudaGetSymbolAddress((void**)&iprev, g_iprev);
    cudaGetSymbolAddress((void**)&iy,  g_iy);
    cudaGetSymbolAddress((void**)&it1, g_it1);
    cudaGetSymbolAddress((void**)&it2, g_it2);
    cudaGetSymbolAddress((void**)&ihc, g_ihc);
    cudaGetSymbolAddress((void**)&wpre, g_wpre);
    cudaGetSymbolAddress((void**)&cnt, g_cnt);
    cudaGetSymbolAddress((void**)&linc, g_linc);
    cudaGetSymbolAddress((void**)&bsum, g_bsum);
    cudaGetSymbolAddress((void**)&bofs, g_bofs);
    cudaGetSymbolAddress((void**)&start, g_start);
    cudaGetSymbolAddress((void**)&cur, g_cur);
    cudaGetSymbolAddress((void**)&ccol, g_ccol);

    cudaFuncSetAttribute(qkv_kernel,     cudaFuncAttributeMaxDynamicSharedMemorySize, SMEM_TOTAL);
    cudaFuncSetAttribute(tgemm<2, 0, 1>, cudaFuncAttributeMaxDynamicSharedMemorySize, SMEM_TOTAL);
    cudaFuncSetAttribute(tgemm<3, 1, 0>, cudaFuncAttributeMaxDynamicSharedMemorySize, SMEM_TOTAL);
    cudaFuncSetAttribute(tgemm<4, 1, 1>, cudaFuncAttributeMaxDynamicSharedMemorySize, SMEM_TOTAL);
    cudaFuncSetAttribute(tgemm<5, 1, 0>, cudaFuncAttributeMaxDynamicSharedMemorySize, SMEM_TOTAL);

    const int gb = (N + 127) / 128;
    const int nb = (N + 255) / 256;
    const float qscale = 0.17677669529663687f;   // 1/sqrt(32)

    // CSR build (deterministic multiblock scan)
    zero_int_kernel<<<(N + 255) / 256, 256>>>(cnt, N);
    hist_kernel<<<(E + 255) / 256, 256>>>(rows, cnt, E);
    scan1_kernel<<<nb, 256>>>(cnt, linc, bsum, N);
    scan2_kernel<<<1, 256>>>(bsum, bofs, nb);
    scan3_kernel<<<nb, 256>>>(bofs, linc, cnt, start, cur, N);
    scatter_kernel<<<(E + 255) / 256, 256>>>(rows, cols, cur, ccol, E);

    // input + weight image conversion
    hconv_kernel<<<dim3((N * 32 + 255) / 256, 2), 256>>>(h_pred, h_prev, ipred, iprev, N);
    WArg wa;
    wa.W[0] = Wq;  wa.W[1] = Wk;  wa.W[2] = Wv;  wa.W[3] = Wo;
    wa.W[4] = Wg2; wa.W[5] = Wm2; wa.W[6] = Wg1; wa.W[7] = Wg1;
    wa.W[8] = Wm1; wa.W[9] = Wm1;
    wconv_kernel<<<dim3(32, 10), 256>>>(wa, wpre);

    // q,k,v projections in one launch (q pre-scaled)
    qkv_kernel<<<dim3(gb, 3), 256, SMEM_TOTAL>>>(ipred, iprev, wpre, bq, bk, bv,
                                                 q, k, v, N, qscale);

    // sparse multi-head attention -> y image
    attn_kernel<<<(N + 7) / 8, 256>>>(q, k, v, ccol, start, cnt, iy, N);

    // gate: t1 = silu([h_pred,h_prev]@Wg1+bg1) (img); g = sigmoid(t1@Wg2+bg2)
    tgemm<2, 0, 1><<<gb, 256, SMEM_TOTAL>>>(ipred, iprev, wpre + 6 * 65536, bg1,
                                            nullptr, nullptr, nullptr, it1, N, 2, 1.f);
    tgemm<3, 1, 0><<<gb, 256, SMEM_TOTAL>>>(it1, nullptr, wpre + 4 * 65536, bg2,
                                            nullptr, nullptr, g, nullptr, N, 1, 1.f);

    // h_corr = h_prev + g * (y@Wo + bo)  (fp32 + img)
    tgemm<4, 1, 1><<<gb, 256, SMEM_TOTAL>>>(iy, nullptr, wpre + 3 * 65536, bo,
                                            g, h_prev, hc, ihc, N, 1, 1.f);

    // fused = h_corr + silu([h_corr,h_prev]@Wm1+bm1)@Wm2+bm2
    tgemm<2, 0, 1><<<gb, 256, SMEM_TOTAL>>>(ihc, iprev, wpre + 8 * 65536, bm1,
                                            nullptr, nullptr, nullptr, it2, N, 2, 1.f);
    tgemm<5, 1, 0><<<gb, 256, SMEM_TOTAL>>>(it2, nullptr, wpre + 5 * 65536, bm2,
                                            hc, nullptr, out, nullptr, N, 1, 1.f);
}

// round 6
// speedup vs baseline: 1.1103x; 1.1103x over previous
#include <cuda_runtime.h>
#include <cuda_bf16.h>
#include <cstdint>
#include <math.h>

#define HID 128
#define NMAX 50000
#define NPAD 50048          // 391*128, covers last tile
#define EMAX 600000
#define IMG_ROW 512         // image row: 256B hi || 256B lo
#define SM_ROW 144          // smem row stride (conflict-free for ldmatrix)
#define SM_IMG 18432        // 128*144
#define SM_BUF 73728        // 4 regions (Ahi,Alo,Bhi,Blo)
#define SMEM_TOTAL 147456   // double buffered

// ---------------- scratch (device globals) ----------------------------------
__device__ float g_q [NMAX * HID];
__device__ float g_k [NMAX * HID];
__device__ float g_v [NMAX * HID];
__device__ float g_g [NMAX * HID];
__device__ float g_hc[NMAX * HID];
__device__ __align__(16) unsigned char g_ipred[(size_t)NPAD * IMG_ROW];
__device__ __align__(16) unsigned char g_iprev[(size_t)NPAD * IMG_ROW];
__device__ __align__(16) unsigned char g_iy  [(size_t)NPAD * IMG_ROW];
__device__ __align__(16) unsigned char g_it1 [(size_t)NPAD * IMG_ROW];
__device__ __align__(16) unsigned char g_it2 [(size_t)NPAD * IMG_ROW];
__device__ __align__(16) unsigned char g_ihc [(size_t)NPAD * IMG_ROW];
__device__ __align__(16) unsigned char g_wpre[10 * 65536];   // 10 weight chunks
__device__ int g_cnt[NMAX];
__device__ int g_linc[NMAX];
__device__ int g_bsum[256];
__device__ int g_bofs[256];
__device__ int g_start[NMAX];
__device__ int g_cur[NMAX];
__device__ int g_ccol[EMAX];

// ---------------- helpers ----------------------------------------------------
__device__ __forceinline__ uint32_t smem_u32(const void* p) {
    uint32_t a;
    asm("{ .reg .u64 t; cvta.to.shared.u64 t, %1; cvt.u32.u64 %0, t; }" : "=r"(a) : "l"(p));
    return a;
}
__device__ __forceinline__ uint32_t pk(float a, float b) {
    __nv_bfloat162 t = __floats2bfloat162_rn(a, b);
    return *reinterpret_cast<uint32_t*>(&t);
}
__device__ __forceinline__ float bf16r(float x) {
    return __bfloat162float(__float2bfloat16(x));
}
__device__ __forceinline__ void ldsm4(uint32_t& r0, uint32_t& r1, uint32_t& r2, uint32_t& r3,
                                      uint32_t addr) {
    asm volatile("ldmatrix.sync.aligned.m8n8.x4.shared.b16 {%0,%1,%2,%3}, [%4];"
                 : "=r"(r0), "=r"(r1), "=r"(r2), "=r"(r3) : "r"(addr));
}
__device__ __forceinline__ void mma16816(float* d, const uint32_t* a, uint32_t b0, uint32_t b1) {
    asm volatile(
        "mma.sync.aligned.m16n8k16.row.col.f32.bf16.bf16.f32 "
        "{%0,%1,%2,%3}, {%4,%5,%6,%7}, {%8,%9}, {%0,%1,%2,%3};"
        : "+f"(d[0]), "+f"(d[1]), "+f"(d[2]), "+f"(d[3])
        : "r"(a[0]), "r"(a[1]), "r"(a[2]), "r"(a[3]), "r"(b0), "r"(b1));
}
__device__ __forceinline__ void cp16(uint32_t saddr, const void* gaddr) {
    asm volatile("cp.async.cg.shared.global [%0], [%1], 16;" :: "r"(saddr), "l"(gaddr));
}

// ---------------- input convert: fp32 -> hi/lo image ------------------------
__global__ void hconv_kernel(const float* __restrict__ hp, const float* __restrict__ hv,
                             unsigned char* __restrict__ ip, unsigned char* __restrict__ iv,
                             int n) {
    int idx = blockIdx.x * blockDim.x + threadIdx.x;
    if (idx >= n * 32) return;
    const float* src = blockIdx.y ? hv : hp;
    unsigned char* dst = blockIdx.y ? iv : ip;
    int row = idx >> 5, sg = idx & 31;
    float4 a = *(const float4*)&src[row * 128 + sg * 4];
    float hx = bf16r(a.x), hy = bf16r(a.y), hz = bf16r(a.z), hw = bf16r(a.w);
    unsigned char* r = dst + (size_t)row * IMG_ROW + sg * 8;
    *(uint2*)(r)       = make_uint2(pk(hx, hy), pk(hz, hw));
    *(uint2*)(r + 256) = make_uint2(pk(a.x - hx, a.y - hy), pk(a.z - hz, a.w - hw));
}

// ---------------- weight convert: all 10 chunks in one launch ----------------
// slots 0-2 (Wq,Wk,Wv): output columns permuted head-major: p = (n&3)*32 + n>>2
// slot 3 (Wo): input rows permuted: image row pair (2kp,2kp+1) <- orig (r, r+4),
//              r = ((2kp)&31)*4 + (2kp)>>5
struct WArg { const float* W[10]; };
__global__ void wconv_kernel(WArg a, unsigned char* __restrict__ dst) {
    int slot = blockIdx.y;
    int idx = blockIdx.x * blockDim.x + threadIdx.x;   // 0..8191
    int n = idx & 127, kp = idx >> 7;                  // kp 0..63
    int kof = (slot == 7 || slot == 9) ? 128 : 0;
    const float* W = a.W[slot];
    float w0, w1;
    int nimg = n;
    if (slot < 3) nimg = (n & 3) * 32 + (n >> 2);
    if (slot == 3) {
        int p = kp * 2;
        int r = ((p & 31) << 2) | (p >> 5);
        w0 = W[r * 128 + n];
        w1 = W[(r + 4) * 128 + n];
    } else {
        int k = kof + kp * 2;
        w0 = W[k * 128 + n];
        w1 = W[(k + 1) * 128 + n];
    }
    float h0 = bf16r(w0), h1 = bf16r(w1);
    unsigned char* base = dst + slot * 65536 + nimg * IMG_ROW + kp * 4;
    *(uint32_t*)(base)       = pk(h0, h1);
    *(uint32_t*)(base + 256) = pk(w0 - h0, w1 - h1);
}

// ---------------- CSR build --------------------------------------------------
__global__ void zero_int_kernel(int* __restrict__ p, int n) {
    int i = blockIdx.x * blockDim.x + threadIdx.x;
    if (i < n) p[i] = 0;
}
__global__ void hist_kernel(const int* __restrict__ rows, int* __restrict__ cnt, int E) {
    int e = blockIdx.x * blockDim.x + threadIdx.x;
    if (e < E) atomicAdd(&cnt[rows[e]], 1);
}
__device__ __forceinline__ int wscan_incl(int x, int lane) {
    #pragma unroll
    for (int o = 1; o < 32; o <<= 1) {
        int t = __shfl_up_sync(0xffffffffu, x, o);
        if (lane >= o) x += t;
    }
    return x;
}
__device__ __forceinline__ int bscan256(int v, int* ws, int tid) {
    int lane = tid & 31, w = tid >> 5;
    int x = wscan_incl(v, lane);
    if (lane == 31) ws[w] = x;
    __syncthreads();
    if (tid < 8) {
        int s = ws[tid];
        #pragma unroll
        for (int o = 1; o < 8; o <<= 1) {
            int t = __shfl_up_sync(0xffu, s, o);
            if (tid >= o) s += t;
        }
        ws[tid] = s;
    }
    __syncthreads();
    return x + (w ? ws[w - 1] : 0);
}
__global__ __launch_bounds__(256) void scan1_kernel(const int* __restrict__ cnt,
                                                    int* __restrict__ linc,
                                                    int* __restrict__ bsum, int n) {
    __shared__ int ws[8];
    int tid = threadIdx.x, i = blockIdx.x * 256 + tid;
    int v = (i < n) ? cnt[i] : 0;
    int incl = bscan256(v, ws, tid);
    if (i < n) linc[i] = incl;
    if (tid == 255) bsum[blockIdx.x] = incl;
}
__global__ __launch_bounds__(256) void scan2_kernel(const int* __restrict__ bsum,
                                                    int* __restrict__ bofs, int nb) {
    __shared__ int ws[8];
    int tid = threadIdx.x;
    int v = (tid < nb) ? bsum[tid] : 0;
    int incl = bscan256(v, ws, tid);
    if (tid < nb) bofs[tid] = incl - v;   // exclusive
}
__global__ void scan3_kernel(const int* __restrict__ bofs, const int* __restrict__ linc,
                             const int* __restrict__ cnt, int* __restrict__ start,
                             int* __restrict__ cur, int n) {
    int i = blockIdx.x * 256 + threadIdx.x;
    if (i < n) {
        int s = bofs[blockIdx.x] + linc[i] - cnt[i];
        start[i] = s;
        cur[i] = s;
    }
}
__global__ void scatter_kernel(const int* __restrict__ rows, const int* __restrict__ cols,
                               int* __restrict__ cur, int* __restrict__ ccol, int E) {
    int e = blockIdx.x * blockDim.x + threadIdx.x;
    if (e < E) {
        int r = rows[e];
        int p = atomicAdd(&cur[r], 1);
        ccol[p] = cols[e];
    }
}

// ---------------- fused sparse attention (one warp per node, head-major) -----
// q/k/v are head-major: col' = h*32 + d. Lane l owns head l>>3, dims (l&7)*4..+3.
// Score reduce = 3 shfl within the 8-lane head group; softmax state scalar/lane.
__global__ __launch_bounds__(256) void attn_kernel(
    const float* __restrict__ q, const float* __restrict__ k, const float* __restrict__ v,
    const int* __restrict__ ccol, const int* __restrict__ start, const int* __restrict__ cnt,
    unsigned char* __restrict__ yimg, int N)
{
    int warp = (blockIdx.x * blockDim.x + threadIdx.x) >> 5;
    int lane = threadIdx.x & 31;
    if (warp >= N) return;
    int node = warp;
    int s = start[node], e = s + cnt[node];

    const float4* q4 = (const float4*)q;
    const float4* k4 = (const float4*)k;
    const float4* v4 = (const float4*)v;

    float4 qv = q4[node * 32 + lane];

    float mx = -INFINITY, lsum = 0.f;
    float4 acc = make_float4(0.f, 0.f, 0.f, 0.f);

    for (int j = s; j < e; j++) {
        int c = __ldg(&ccol[j]);
        float4 kv = k4[c * 32 + lane];
        float sc = qv.x * kv.x + qv.y * kv.y + qv.z * kv.z + qv.w * kv.w;
        sc += __shfl_xor_sync(0xffffffffu, sc, 1);
        sc += __shfl_xor_sync(0xffffffffu, sc, 2);
        sc += __shfl_xor_sync(0xffffffffu, sc, 4);
        float4 vv = v4[c * 32 + lane];
        if (sc > mx) {
            float cf = __expf(mx - sc);
            lsum *= cf;
            acc.x *= cf; acc.y *= cf; acc.z *= cf; acc.w *= cf;
            mx = sc;
        }
        float p = __expf(sc - mx);
        lsum += p;
        acc.x += p * vv.x; acc.y += p * vv.y;
        acc.z += p * vv.z; acc.w += p * vv.w;
    }
    float inv = lsum > 0.f ? 1.f / lsum : 0.f;
    float ox = acc.x * inv, oy = acc.y * inv, oz = acc.z * inv, ow = acc.w * inv;
    float hx = bf16r(ox), hy = bf16r(oy), hz = bf16r(oz), hw = bf16r(ow);
    unsigned char* yr = yimg + (size_t)node * IMG_ROW + lane * 8;
    *(uint2*)(yr)       = make_uint2(pk(hx, hy), pk(hz, hw));
    *(uint2*)(yr + 256) = make_uint2(pk(ox - hx, oy - hy), pk(oz - hz, ow - hw));
}

// ---------------- pipelined HMMA bf16-split GEMM -----------------------------
// A,B are hi/lo images (IMG_ROW 512B rows). K = nchunk*128, 2 substages/chunk.
// EPI: 1 *scale | 2 silu | 3 sigmoid | 4 C=P2+P1*val | 5 C=val+P1
// WF: write fp32 Cf, WI: write hi/lo image Cimg, PERM: bias head-major permuted
__device__ __forceinline__ void stage_cp(uint32_t sbuf, const unsigned char* Aimg,
                                         const unsigned char* Bc, int h, int tid, int bm) {
    #pragma unroll
    for (int i = 0; i < 16; i++) {
        int t = tid + i * 256;
        int region = t >> 10, row = (t >> 3) & 127, sg = t & 7;
        int lo = (region & 1) * 256;
        const unsigned char* g = (region < 2)
            ? Aimg + (size_t)(bm + row) * IMG_ROW + lo + h * 128 + sg * 16
            : Bc   + row * IMG_ROW + lo + h * 128 + sg * 16;
        cp16(sbuf + region * SM_IMG + row * SM_ROW + sg * 16, g);
    }
    asm volatile("cp.async.commit_group;" ::: "memory");
}

template<int EPI, int WF, int WI, int PERM>
__device__ __forceinline__ void gemm_body(
    const unsigned char* __restrict__ A1, const unsigned char* __restrict__ A2,
    const unsigned char* __restrict__ B, const float* __restrict__ bias,
    const float* __restrict__ P1, const float* __restrict__ P2,
    float* __restrict__ Cf, unsigned char* __restrict__ Cimg,
    int M, int nchunk, float scale, char* smem, int bm)
{
    const uint32_t sb = smem_u32(smem);
    const int tid = threadIdx.x, wid = tid >> 5, lane = tid & 31;
    const int wm = (wid & 3) * 32, wn = (wid >> 2) * 64;
    const int S = nchunk * 2;

    float acc[2][8][4];
    #pragma unroll
    for (int mt = 0; mt < 2; mt++)
        #pragma unroll
        for (int nt = 0; nt < 8; nt++)
            #pragma unroll
            for (int r = 0; r < 4; r++) acc[mt][nt][r] = 0.f;

    stage_cp(sb, A1, B, 0, tid, bm);
    stage_cp(sb + SM_BUF, A1, B, 1, tid, bm);   // s=1 is always chunk 0

    const int lrow = lane & 15, lc16 = (lane >> 4) * 16;

    for (int s = 0; s < S; s++) {
        if (s + 1 < S) asm volatile("cp.async.wait_group 1;" ::: "memory");
        else           asm volatile("cp.async.wait_group 0;" ::: "memory");
        __syncthreads();
        const uint32_t base = sb + (s & 1) * SM_BUF;
        #pragma unroll
        for (int ks = 0; ks < 4; ks++) {
            const uint32_t kb = (uint32_t)(ks * 32);
            uint32_t ah[2][4], al[2][4], bh[8][2], bl[8][2];
            #pragma unroll
            for (int mt = 0; mt < 2; mt++) {
                uint32_t ad = base + (wm + mt * 16 + lrow) * SM_ROW + lc16 + kb;
                ldsm4(ah[mt][0], ah[mt][1], ah[mt][2], ah[mt][3], ad);
                ldsm4(al[mt][0], al[mt][1], al[mt][2], al[mt][3], ad + SM_IMG);
            }
            #pragma unroll
            for (int j = 0; j < 4; j++) {
                uint32_t bd = base + 2 * SM_IMG + (wn + j * 16 + lrow) * SM_ROW + lc16 + kb;
                uint32_t r0, r1, r2, r3;
                ldsm4(r0, r1, r2, r3, bd);
                bh[2*j][0] = r0; bh[2*j+1][0] = r1; bh[2*j][1] = r2; bh[2*j+1][1] = r3;
                ldsm4(r0, r1, r2, r3, bd + SM_IMG);
                bl[2*j][0] = r0; bl[2*j+1][0] = r1; bl[2*j][1] = r2; bl[2*j+1][1] = r3;
            }
            #pragma unroll
            for (int mt = 0; mt < 2; mt++)
                #pragma unroll
                for (int nt = 0; nt < 8; nt++) {
                    mma16816(acc[mt][nt], ah[mt], bh[nt][0], bh[nt][1]);
                    mma16816(acc[mt][nt], ah[mt], bl[nt][0], bl[nt][1]);
                    mma16816(acc[mt][nt], al[mt], bh[nt][0], bh[nt][1]);
                }
        }
        __syncthreads();
        if (s + 2 < S) {
            int ns = s + 2;
            const unsigned char* Ai = (ns >= 2) ? A2 : A1;
            stage_cp(sb + (s & 1) * SM_BUF, Ai, B + (ns >> 1) * 65536, ns & 1, tid, bm);
        }
    }

    // epilogue from register accumulators
    #pragma unroll
    for (int mt = 0; mt < 2; mt++) {
        #pragma unroll
        for (int half = 0; half < 2; half++) {
            int row = bm + wm + mt * 16 + (lane >> 2) + half * 8;
            if (row < M) {
                #pragma unroll
                for (int nt = 0; nt < 8; nt++) {
                    int col = wn + nt * 8 + 2 * (lane & 3);
                    float b0, b1;
                    if (PERM) {
                        int n0 = ((col & 31) << 2) | (col >> 5);
                        b0 = __ldg(&bias[n0]);
                        b1 = __ldg(&bias[n0 + 4]);
                    } else {
                        float2 bs = *(const float2*)&bias[col];
                        b0 = bs.x; b1 = bs.y;
                    }
                    float v0 = acc[mt][nt][half * 2 + 0] + b0;
                    float v1 = acc[mt][nt][half * 2 + 1] + b1;
                    if (EPI == 1) { v0 *= scale; v1 *= scale; }
                    if (EPI == 2) { v0 = v0 / (1.f + __expf(-v0)); v1 = v1 / (1.f + __expf(-v1)); }
                    if (EPI == 3) { v0 = 1.f / (1.f + __expf(-v0)); v1 = 1.f / (1.f + __expf(-v1)); }
                    int idx = row * 128 + col;
                    if (EPI == 4) {
                        float2 gm = *(const float2*)&P1[idx];
                        float2 hp = *(const float2*)&P2[idx];
                        v0 = hp.x + gm.x * v0;
                        v1 = hp.y + gm.y * v1;
                    } else if (EPI == 5) {
                        float2 ad = *(const float2*)&P1[idx];
                        v0 += ad.x; v1 += ad.y;
                    }
                    if (WF) *(float2*)&Cf[idx] = make_float2(v0, v1);
                    if (WI) {
                        float h0 = bf16r(v0), h1 = bf16r(v1);
                        unsigned char* r = Cimg + (size_t)row * IMG_ROW + col * 2;
                        *(uint32_t*)(r)       = pk(h0, h1);
                        *(uint32_t*)(r + 256) = pk(v0 - h0, v1 - h1);
                    }
                }
            }
        }
    }
}

template<int EPI, int WF, int WI>
__global__ __launch_bounds__(256, 1) void tgemm(
    const unsigned char* __restrict__ A1, const unsigned char* __restrict__ A2,
    const unsigned char* __restrict__ B, const float* __restrict__ bias,
    const float* __restrict__ P1, const float* __restrict__ P2,
    float* __restrict__ Cf, unsigned char* __restrict__ Cimg,
    int M, int nchunk, float scale)
{
    extern __shared__ char smem[];
    gemm_body<EPI, WF, WI, 0>(A1, A2, B, bias, P1, P2, Cf, Cimg, M, nchunk, scale,
                              smem, blockIdx.x * 128);
}

// y=0..2: q/k/v projections (head-major outputs, permuted bias); y=3: gate t1
__global__ __launch_bounds__(256, 1) void qkvt_kernel(
    const unsigned char* __restrict__ ipred, const unsigned char* __restrict__ iprev,
    const unsigned char* __restrict__ wpre,
    const float* __restrict__ bq, const float* __restrict__ bk, const float* __restrict__ bv,
    const float* __restrict__ bg1,
    float* __restrict__ q, float* __restrict__ k, float* __restrict__ v,
    unsigned char* __restrict__ it1,
    int M, float qs)
{
    extern __shared__ char smem[];
    int y = blockIdx.y;
    int bm = blockIdx.x * 128;
    if (y < 3) {
        const unsigned char* A = (y == 1) ? iprev : ipred;
        const unsigned char* B = wpre + y * 65536;
        const float* bias = (y == 0) ? bq : (y == 1) ? bk : bv;
        float* C = (y == 0) ? q : (y == 1) ? k : v;
        float sc = (y == 0) ? qs : 1.f;
        gemm_body<1, 1, 0, 1>(A, nullptr, B, bias, nullptr, nullptr, C, nullptr,
                              M, 1, sc, smem, bm);
    } else {
        gemm_body<2, 0, 1, 0>(ipred, iprev, wpre + 6 * 65536, bg1, nullptr, nullptr,
                              nullptr, it1, M, 2, 1.f, smem, bm);
    }
}

// ---------------- launch -----------------------------------------------------
extern "C" void kernel_launch(void* const* d_in, const int* in_sizes, int n_in,
                              void* d_out, int out_size) {
    const float* h_prev = (const float*)d_in[0];
    const float* h_pred = (const float*)d_in[1];
    const float* Wq  = (const float*)d_in[2];  const float* bq  = (const float*)d_in[3];
    const float* Wk  = (const float*)d_in[4];  const float* bk  = (const float*)d_in[5];
    const float* Wv  = (const float*)d_in[6];  const float* bv  = (const float*)d_in[7];
    const float* Wo  = (const float*)d_in[8];  const float* bo  = (const float*)d_in[9];
    const float* Wg1 = (const float*)d_in[10]; const float* bg1 = (const float*)d_in[11];
    const float* Wg2 = (const float*)d_in[12]; const float* bg2 = (const float*)d_in[13];
    const float* Wm1 = (const float*)d_in[14]; const float* bm1 = (const float*)d_in[15];
    const float* Wm2 = (const float*)d_in[16]; const float* bm2 = (const float*)d_in[17];
    const int* rows  = (const int*)d_in[18];
    const int* cols  = (const int*)d_in[19];
    const int N = in_sizes[0] / HID;
    const int E = in_sizes[18];
    float* out = (float*)d_out;

    float *q, *k, *v, *g, *hc;
    int *cnt, *linc, *bsum, *bofs, *start, *cur, *ccol;
    unsigned char *ipred, *iprev, *iy, *it1, *it2, *ihc, *wpre;
    cudaGetSymbolAddress((void**)&q,   g_q);
    cudaGetSymbolAddress((void**)&k,   g_k);
    cudaGetSymbolAddress((void**)&v,   g_v);
    cudaGetSymbolAddress((void**)&g,   g_g);
    cudaGetSymbolAddress((void**)&hc,  g_hc);
    cudaGetSymbolAddress((void**)&ipred, g_ipred);
    cudaGetSymbolAddress((void**)&iprev, g_iprev);
    cudaGetSymbolAddress((void**)&iy,  g_iy);
    cudaGetSymbolAddress((void**)&it1, g_it1);
    cudaGetSymbolAddress((void**)&it2, g_it2);
    cudaGetSymbolAddress((void**)&ihc, g_ihc);
    cudaGetSymbolAddress((void**)&wpre, g_wpre);
    cudaGetSymbolAddress((void**)&cnt, g_cnt);
    cudaGetSymbolAddress((void**)&linc, g_linc);
    cudaGetSymbolAddress((void**)&bsum, g_bsum);
    cudaGetSymbolAddress((void**)&bofs, g_bofs);
    cudaGetSymbolAddress((void**)&start, g_start);
    cudaGetSymbolAddress((void**)&cur, g_cur);
    cudaGetSymbolAddress((void**)&ccol, g_ccol);

    cudaFuncSetAttribute(qkvt_kernel,    cudaFuncAttributeMaxDynamicSharedMemorySize, SMEM_TOTAL);
    cudaFuncSetAttribute(tgemm<2, 0, 1>, cudaFuncAttributeMaxDynamicSharedMemorySize, SMEM_TOTAL);
    cudaFuncSetAttribute(tgemm<3, 1, 0>, cudaFuncAttributeMaxDynamicSharedMemorySize, SMEM_TOTAL);
    cudaFuncSetAttribute(tgemm<4, 1, 1>, cudaFuncAttributeMaxDynamicSharedMemorySize, SMEM_TOTAL);
    cudaFuncSetAttribute(tgemm<5, 1, 0>, cudaFuncAttributeMaxDynamicSharedMemorySize, SMEM_TOTAL);

    const int gb = (N + 127) / 128;
    const int nb = (N + 255) / 256;
    const float qscale = 0.17677669529663687f;   // 1/sqrt(32)

    // CSR build (deterministic multiblock scan)
    zero_int_kernel<<<(N + 255) / 256, 256>>>(cnt, N);
    hist_kernel<<<(E + 255) / 256, 256>>>(rows, cnt, E);
    scan1_kernel<<<nb, 256>>>(cnt, linc, bsum, N);
    scan2_kernel<<<1, 256>>>(bsum, bofs, nb);
    scan3_kernel<<<nb, 256>>>(bofs, linc, cnt, start, cur, N);
    scatter_kernel<<<(E + 255) / 256, 256>>>(rows, cols, cur, ccol, E);

    // input + weight image conversion
    hconv_kernel<<<dim3((N * 32 + 255) / 256, 2), 256>>>(h_pred, h_prev, ipred, iprev, N);
    WArg wa;
    wa.W[0] = Wq;  wa.W[1] = Wk;  wa.W[2] = Wv;  wa.W[3] = Wo;
    wa.W[4] = Wg2; wa.W[5] = Wm2; wa.W[6] = Wg1; wa.W[7] = Wg1;
    wa.W[8] = Wm1; wa.W[9] = Wm1;
    wconv_kernel<<<dim3(32, 10), 256>>>(wa, wpre);

    // q,k,v projections + gate t1 in one launch
    qkvt_kernel<<<dim3(gb, 4), 256, SMEM_TOTAL>>>(ipred, iprev, wpre, bq, bk, bv, bg1,
                                                  q, k, v, it1, N, qscale);

    // sparse multi-head attention (head-major) -> y image
    attn_kernel<<<(N + 7) / 8, 256>>>(q, k, v, ccol, start, cnt, iy, N);

    // g = sigmoid(t1@Wg2+bg2)
    tgemm<3, 1, 0><<<gb, 256, SMEM_TOTAL>>>(it1, nullptr, wpre + 4 * 65536, bg2,
                                            nullptr, nullptr, g, nullptr, N, 1, 1.f);

    // h_corr = h_prev + g * (y@Wo + bo)  (fp32 + img); Wo rows pre-permuted
    tgemm<4, 1, 1><<<gb, 256, SMEM_TOTAL>>>(iy, nullptr, wpre + 3 * 65536, bo,
                                            g, h_prev, hc, ihc, N, 1, 1.f);

    // fused = h_corr + silu([h_corr,h_prev]@Wm1+bm1)@Wm2+bm2
    tgemm<2, 0, 1><<<gb, 256, SMEM_TOTAL>>>(ihc, iprev, wpre + 8 * 65536, bm1,
                                            nullptr, nullptr, nullptr, it2, N, 2, 1.f);
    tgemm<5, 1, 0><<<gb, 256, SMEM_TOTAL>>>(it2, nullptr, wpre + 5 * 65536, bm2,
                                            hc, nullptr, out, nullptr, N, 1, 1.f);
}

// round 7
// speedup vs baseline: 1.1443x; 1.0307x over previous
#include <cuda_runtime.h>
#include <cuda_bf16.h>
#include <cstdint>
#include <math.h>

#define HID 128
#define NMAX 50000
#define NPAD 50048          // 391*128, covers last tile
#define EMAX 600000
#define IMG_ROW 512         // image row: 256B hi || 256B lo
#define SM_ROW 144          // smem row stride (conflict-free for ldmatrix)
#define SM_IMG 18432        // 128*144
#define SM_BUF 73728        // 4 regions (Ahi,Alo,Bhi,Blo)
#define SMEM_TOTAL 147456   // double buffered

// ---------------- scratch (device globals) ----------------------------------
__device__ float g_q [NMAX * HID];
__device__ float g_k [NMAX * HID];
__device__ float g_v [NMAX * HID];
__device__ __align__(16) unsigned char g_ipred[(size_t)NPAD * IMG_ROW];
__device__ __align__(16) unsigned char g_iprev[(size_t)NPAD * IMG_ROW];
__device__ __align__(16) unsigned char g_iy  [(size_t)NPAD * IMG_ROW];
__device__ __align__(16) unsigned char g_ihc [(size_t)NPAD * IMG_ROW];
__device__ __align__(16) unsigned char g_wpre[10 * 65536];   // 10 weight chunks
__device__ int g_cnt[NMAX];
__device__ int g_linc[NMAX];
__device__ int g_bsum[256];
__device__ int g_bofs[256];
__device__ int g_start[NMAX];
__device__ int g_cur[NMAX];
__device__ int g_ccol[EMAX];

// ---------------- helpers ----------------------------------------------------
__device__ __forceinline__ uint32_t smem_u32(const void* p) {
    uint32_t a;
    asm("{ .reg .u64 t; cvta.to.shared.u64 t, %1; cvt.u32.u64 %0, t; }" : "=r"(a) : "l"(p));
    return a;
}
__device__ __forceinline__ uint32_t pk(float a, float b) {
    __nv_bfloat162 t = __floats2bfloat162_rn(a, b);
    return *reinterpret_cast<uint32_t*>(&t);
}
__device__ __forceinline__ float2 unpk(uint32_t u) {
    __nv_bfloat162 t = *reinterpret_cast<__nv_bfloat162*>(&u);
    return make_float2(__bfloat162float(t.x), __bfloat162float(t.y));
}
__device__ __forceinline__ float bf16r(float x) {
    return __bfloat162float(__float2bfloat16(x));
}
__device__ __forceinline__ void ldsm4(uint32_t& r0, uint32_t& r1, uint32_t& r2, uint32_t& r3,
                                      uint32_t addr) {
    asm volatile("ldmatrix.sync.aligned.m8n8.x4.shared.b16 {%0,%1,%2,%3}, [%4];"
                 : "=r"(r0), "=r"(r1), "=r"(r2), "=r"(r3) : "r"(addr));
}
__device__ __forceinline__ void mma16816(float* d, const uint32_t* a, uint32_t b0, uint32_t b1) {
    asm volatile(
        "mma.sync.aligned.m16n8k16.row.col.f32.bf16.bf16.f32 "
        "{%0,%1,%2,%3}, {%4,%5,%6,%7}, {%8,%9}, {%0,%1,%2,%3};"
        : "+f"(d[0]), "+f"(d[1]), "+f"(d[2]), "+f"(d[3])
        : "r"(a[0]), "r"(a[1]), "r"(a[2]), "r"(a[3]), "r"(b0), "r"(b1));
}
__device__ __forceinline__ void cp16(uint32_t saddr, const void* gaddr) {
    asm volatile("cp.async.cg.shared.global [%0], [%1], 16;" :: "r"(saddr), "l"(gaddr));
}
__device__ __forceinline__ void sts32(uint32_t a, uint32_t v) {
    asm volatile("st.shared.b32 [%0], %1;" :: "r"(a), "r"(v));
}
#define CP_COMMIT() asm volatile("cp.async.commit_group;" ::: "memory")
#define CP_WAIT(n)  asm volatile("cp.async.wait_group " #n ";" ::: "memory")

// stage one substage (64 K-cols): A image (128 rows @ bm) + B chunk, half h
__device__ __forceinline__ void stage_cp(uint32_t sbuf, const unsigned char* Aimg,
                                         const unsigned char* Bc, int h, int tid, int bm) {
    #pragma unroll
    for (int i = 0; i < 16; i++) {
        int t = tid + i * 256;
        int region = t >> 10, row = (t >> 3) & 127, sg = t & 7;
        int lo = (region & 1) * 256;
        const unsigned char* g = (region < 2)
            ? Aimg + (size_t)(bm + row) * IMG_ROW + lo + h * 128 + sg * 16
            : Bc   + row * IMG_ROW + lo + h * 128 + sg * 16;
        cp16(sbuf + region * SM_IMG + row * SM_ROW + sg * 16, g);
    }
    CP_COMMIT();
}
// stage only B regions (for second-stage weights)
__device__ __forceinline__ void stage_cp_B(uint32_t sbuf, const unsigned char* Bc,
                                           int h, int tid) {
    #pragma unroll
    for (int i = 0; i < 8; i++) {
        int t = tid + i * 256;
        int reg = t >> 10, row = (t >> 3) & 127, sg = t & 7;
        const unsigned char* g = Bc + row * IMG_ROW + reg * 256 + h * 128 + sg * 16;
        cp16(sbuf + (2 + reg) * SM_IMG + row * SM_ROW + sg * 16, g);
    }
    CP_COMMIT();
}

// one 64-K substage of 3-term split MMA from smem buffer `base`
__device__ __forceinline__ void mma_substage(float (&acc)[2][8][4], uint32_t base,
                                             int wm, int wn, int lrow, int lc16) {
    #pragma unroll
    for (int ks = 0; ks < 4; ks++) {
        const uint32_t kb = (uint32_t)(ks * 32);
        uint32_t ah[2][4], al[2][4], bh[8][2], bl[8][2];
        #pragma unroll
        for (int mt = 0; mt < 2; mt++) {
            uint32_t ad = base + (wm + mt * 16 + lrow) * SM_ROW + lc16 + kb;
            ldsm4(ah[mt][0], ah[mt][1], ah[mt][2], ah[mt][3], ad);
            ldsm4(al[mt][0], al[mt][1], al[mt][2], al[mt][3], ad + SM_IMG);
        }
        #pragma unroll
        for (int j = 0; j < 4; j++) {
            uint32_t bd = base + 2 * SM_IMG + (wn + j * 16 + lrow) * SM_ROW + lc16 + kb;
            uint32_t r0, r1, r2, r3;
            ldsm4(r0, r1, r2, r3, bd);
            bh[2*j][0] = r0; bh[2*j+1][0] = r1; bh[2*j][1] = r2; bh[2*j+1][1] = r3;
            ldsm4(r0, r1, r2, r3, bd + SM_IMG);
            bl[2*j][0] = r0; bl[2*j+1][0] = r1; bl[2*j][1] = r2; bl[2*j+1][1] = r3;
        }
        #pragma unroll
        for (int mt = 0; mt < 2; mt++)
            #pragma unroll
            for (int nt = 0; nt < 8; nt++) {
                mma16816(acc[mt][nt], ah[mt], bh[nt][0], bh[nt][1]);
                mma16816(acc[mt][nt], ah[mt], bl[nt][0], bl[nt][1]);
                mma16816(acc[mt][nt], al[mt], bh[nt][0], bh[nt][1]);
            }
    }
}

// store silu(acc+bias) as hi/lo tiles into smem A-regions (staged-A layout):
// cols 0-63 -> buf0 (sb), cols 64-127 -> buf1 (sb+SM_BUF)
__device__ __forceinline__ void store_silu_tile(const float (&acc)[2][8][4],
    const float* __restrict__ bias, uint32_t sb, int wm, int wn, int lane) {
    #pragma unroll
    for (int mt = 0; mt < 2; mt++)
        #pragma unroll
        for (int half = 0; half < 2; half++) {
            int row = wm + mt * 16 + (lane >> 2) + half * 8;
            #pragma unroll
            for (int nt = 0; nt < 8; nt++) {
                int col = wn + nt * 8 + 2 * (lane & 3);
                float2 bs = *(const float2*)&bias[col];
                float v0 = acc[mt][nt][half * 2 + 0] + bs.x;
                float v1 = acc[mt][nt][half * 2 + 1] + bs.y;
                v0 = v0 / (1.f + __expf(-v0));
                v1 = v1 / (1.f + __expf(-v1));
                float h0 = bf16r(v0), h1 = bf16r(v1);
                uint32_t buf = sb + ((col >= 64) ? (uint32_t)SM_BUF : 0u);
                uint32_t off = (uint32_t)(row * SM_ROW + (col & 63) * 2);
                sts32(buf + off, pk(h0, h1));
                sts32(buf + SM_IMG + off, pk(v0 - h0, v1 - h1));
            }
        }
}

// ---------------- input convert: fp32 -> hi/lo image ------------------------
__global__ void hconv_kernel(const float* __restrict__ hp, const float* __restrict__ hv,
                             unsigned char* __restrict__ ip, unsigned char* __restrict__ iv,
                             int n) {
    int idx = blockIdx.x * blockDim.x + threadIdx.x;
    if (idx >= n * 32) return;
    const float* src = blockIdx.y ? hv : hp;
    unsigned char* dst = blockIdx.y ? iv : ip;
    int row = idx >> 5, sg = idx & 31;
    float4 a = *(const float4*)&src[row * 128 + sg * 4];
    float hx = bf16r(a.x), hy = bf16r(a.y), hz = bf16r(a.z), hw = bf16r(a.w);
    unsigned char* r = dst + (size_t)row * IMG_ROW + sg * 8;
    *(uint2*)(r)       = make_uint2(pk(hx, hy), pk(hz, hw));
    *(uint2*)(r + 256) = make_uint2(pk(a.x - hx, a.y - hy), pk(a.z - hz, a.w - hw));
}

// ---------------- weight convert: all 10 chunks in one launch ----------------
// slots 0-2 (Wq,Wk,Wv): output columns permuted head-major: p = (n&3)*32 + n>>2
// slot 3 (Wo): input rows permuted to match head-major y
struct WArg { const float* W[10]; };
__global__ void wconv_kernel(WArg a, unsigned char* __restrict__ dst) {
    int slot = blockIdx.y;
    int idx = blockIdx.x * blockDim.x + threadIdx.x;   // 0..8191
    int n = idx & 127, kp = idx >> 7;                  // kp 0..63
    int kof = (slot == 7 || slot == 9) ? 128 : 0;
    const float* W = a.W[slot];
    float w0, w1;
    int nimg = n;
    if (slot < 3) nimg = (n & 3) * 32 + (n >> 2);
    if (slot == 3) {
        int p = kp * 2;
        int r = ((p & 31) << 2) | (p >> 5);
        w0 = W[r * 128 + n];
        w1 = W[(r + 4) * 128 + n];
    } else {
        int k = kof + kp * 2;
        w0 = W[k * 128 + n];
        w1 = W[(k + 1) * 128 + n];
    }
    float h0 = bf16r(w0), h1 = bf16r(w1);
    unsigned char* base = dst + slot * 65536 + nimg * IMG_ROW + kp * 4;
    *(uint32_t*)(base)       = pk(h0, h1);
    *(uint32_t*)(base + 256) = pk(w0 - h0, w1 - h1);
}

// ---------------- CSR build --------------------------------------------------
__global__ void zero_int_kernel(int* __restrict__ p, int n) {
    int i = blockIdx.x * blockDim.x + threadIdx.x;
    if (i < n) p[i] = 0;
}
__global__ void hist_kernel(const int* __restrict__ rows, int* __restrict__ cnt, int E) {
    int e = blockIdx.x * blockDim.x + threadIdx.x;
    if (e < E) atomicAdd(&cnt[rows[e]], 1);
}
__device__ __forceinline__ int wscan_incl(int x, int lane) {
    #pragma unroll
    for (int o = 1; o < 32; o <<= 1) {
        int t = __shfl_up_sync(0xffffffffu, x, o);
        if (lane >= o) x += t;
    }
    return x;
}
__device__ __forceinline__ int bscan256(int v, int* ws, int tid) {
    int lane = tid & 31, w = tid >> 5;
    int x = wscan_incl(v, lane);
    if (lane == 31) ws[w] = x;
    __syncthreads();
    if (tid < 8) {
        int s = ws[tid];
        #pragma unroll
        for (int o = 1; o < 8; o <<= 1) {
            int t = __shfl_up_sync(0xffu, s, o);
            if (tid >= o) s += t;
        }
        ws[tid] = s;
    }
    __syncthreads();
    return x + (w ? ws[w - 1] : 0);
}
__global__ __launch_bounds__(256) void scan1_kernel(const int* __restrict__ cnt,
                                                    int* __restrict__ linc,
                                                    int* __restrict__ bsum, int n) {
    __shared__ int ws[8];
    int tid = threadIdx.x, i = blockIdx.x * 256 + tid;
    int v = (i < n) ? cnt[i] : 0;
    int incl = bscan256(v, ws, tid);
    if (i < n) linc[i] = incl;
    if (tid == 255) bsum[blockIdx.x] = incl;
}
__global__ __launch_bounds__(256) void scan2_kernel(const int* __restrict__ bsum,
                                                    int* __restrict__ bofs, int nb) {
    __shared__ int ws[8];
    int tid = threadIdx.x;
    int v = (tid < nb) ? bsum[tid] : 0;
    int incl = bscan256(v, ws, tid);
    if (tid < nb) bofs[tid] = incl - v;   // exclusive
}
__global__ void scan3_kernel(const int* __restrict__ bofs, const int* __restrict__ linc,
                             const int* __restrict__ cnt, int* __restrict__ start,
                             int* __restrict__ cur, int n) {
    int i = blockIdx.x * 256 + threadIdx.x;
    if (i < n) {
        int s = bofs[blockIdx.x] + linc[i] - cnt[i];
        start[i] = s;
        cur[i] = s;
    }
}
__global__ void scatter_kernel(const int* __restrict__ rows, const int* __restrict__ cols,
                               int* __restrict__ cur, int* __restrict__ ccol, int E) {
    int e = blockIdx.x * blockDim.x + threadIdx.x;
    if (e < E) {
        int r = rows[e];
        int p = atomicAdd(&cur[r], 1);
        ccol[p] = cols[e];
    }
}

// ---------------- fused sparse attention (one warp per node, head-major) -----
__global__ __launch_bounds__(256) void attn_kernel(
    const float* __restrict__ q, const float* __restrict__ k, const float* __restrict__ v,
    const int* __restrict__ ccol, const int* __restrict__ start, const int* __restrict__ cnt,
    unsigned char* __restrict__ yimg, int N)
{
    int warp = (blockIdx.x * blockDim.x + threadIdx.x) >> 5;
    int lane = threadIdx.x & 31;
    if (warp >= N) return;
    int node = warp;
    int s = start[node], e = s + cnt[node];

    const float4* q4 = (const float4*)q;
    const float4* k4 = (const float4*)k;
    const float4* v4 = (const float4*)v;

    float4 qv = q4[node * 32 + lane];

    float mx = -INFINITY, lsum = 0.f;
    float4 acc = make_float4(0.f, 0.f, 0.f, 0.f);

    for (int j = s; j < e; j++) {
        int c = __ldg(&ccol[j]);
        float4 kv = k4[c * 32 + lane];
        float sc = qv.x * kv.x + qv.y * kv.y + qv.z * kv.z + qv.w * kv.w;
        sc += __shfl_xor_sync(0xffffffffu, sc, 1);
        sc += __shfl_xor_sync(0xffffffffu, sc, 2);
        sc += __shfl_xor_sync(0xffffffffu, sc, 4);
        float4 vv = v4[c * 32 + lane];
        if (sc > mx) {
            float cf = __expf(mx - sc);
            lsum *= cf;
            acc.x *= cf; acc.y *= cf; acc.z *= cf; acc.w *= cf;
            mx = sc;
        }
        float p = __expf(sc - mx);
        lsum += p;
        acc.x += p * vv.x; acc.y += p * vv.y;
        acc.z += p * vv.z; acc.w += p * vv.w;
    }
    float inv = lsum > 0.f ? 1.f / lsum : 0.f;
    float ox = acc.x * inv, oy = acc.y * inv, oz = acc.z * inv, ow = acc.w * inv;
    float hx = bf16r(ox), hy = bf16r(oy), hz = bf16r(oz), hw = bf16r(ow);
    unsigned char* yr = yimg + (size_t)node * IMG_ROW + lane * 8;
    *(uint2*)(yr)       = make_uint2(pk(hx, hy), pk(hz, hw));
    *(uint2*)(yr + 256) = make_uint2(pk(ox - hx, oy - hy), pk(oz - hz, ow - hw));
}

// ---------------- qkv projections (single-chunk GEMM, head-major epi) --------
__global__ __launch_bounds__(256, 1) void qkv_kernel(
    const unsigned char* __restrict__ ipred, const unsigned char* __restrict__ iprev,
    const unsigned char* __restrict__ wpre,
    const float* __restrict__ bq, const float* __restrict__ bk, const float* __restrict__ bv,
    float* __restrict__ q, float* __restrict__ k, float* __restrict__ v,
    int M, float qs)
{
    extern __shared__ char smem[];
    const uint32_t sb = smem_u32(smem);
    int y = blockIdx.y;
    const unsigned char* A = (y == 1) ? iprev : ipred;
    const unsigned char* B = wpre + y * 65536;
    const float* bias = (y == 0) ? bq : (y == 1) ? bk : bv;
    float* C = (y == 0) ? q : (y == 1) ? k : v;
    float sc = (y == 0) ? qs : 1.f;

    const int tid = threadIdx.x, wid = tid >> 5, lane = tid & 31;
    const int wm = (wid & 3) * 32, wn = (wid >> 2) * 64;
    const int bm = blockIdx.x * 128;
    const int lrow = lane & 15, lc16 = (lane >> 4) * 16;

    float acc[2][8][4];
    #pragma unroll
    for (int mt = 0; mt < 2; mt++)
        #pragma unroll
        for (int nt = 0; nt < 8; nt++)
            #pragma unroll
            for (int r = 0; r < 4; r++) acc[mt][nt][r] = 0.f;

    stage_cp(sb, A, B, 0, tid, bm);
    stage_cp(sb + SM_BUF, A, B, 1, tid, bm);
    CP_WAIT(1); __syncthreads();
    mma_substage(acc, sb, wm, wn, lrow, lc16);
    CP_WAIT(0); __syncthreads();
    mma_substage(acc, sb + SM_BUF, wm, wn, lrow, lc16);

    #pragma unroll
    for (int mt = 0; mt < 2; mt++)
        #pragma unroll
        for (int half = 0; half < 2; half++) {
            int row = bm + wm + mt * 16 + (lane >> 2) + half * 8;
            if (row < M) {
                #pragma unroll
                for (int nt = 0; nt < 8; nt++) {
                    int col = wn + nt * 8 + 2 * (lane & 3);
                    int n0 = ((col & 31) << 2) | (col >> 5);
                    float v0 = (acc[mt][nt][half * 2 + 0] + __ldg(&bias[n0])) * sc;
                    float v1 = (acc[mt][nt][half * 2 + 1] + __ldg(&bias[n0 + 4])) * sc;
                    *(float2*)&C[row * 128 + col] = make_float2(v0, v1);
                }
            }
        }
}

// ---------------- gatehc: O=y@Wo, T1=silu(cat@Wg1), G=T1@Wg2 (in-smem),
//                  hc = h_prev + sigmoid(G+bg2)*(O+bo) -> ihc image ----------
__global__ __launch_bounds__(256, 1) void gatehc_kernel(
    const unsigned char* __restrict__ iy, const unsigned char* __restrict__ ipred,
    const unsigned char* __restrict__ iprev, const unsigned char* __restrict__ wpre,
    const float* __restrict__ bo, const float* __restrict__ bg1,
    const float* __restrict__ bg2, const float* __restrict__ h_prev,
    unsigned char* __restrict__ ihc, int M)
{
    extern __shared__ char smem[];
    const uint32_t sb = smem_u32(smem);
    const int tid = threadIdx.x, wid = tid >> 5, lane = tid & 31;
    const int wm = (wid & 3) * 32, wn = (wid >> 2) * 64;
    const int bm = blockIdx.x * 128;
    const int lrow = lane & 15, lc16 = (lane >> 4) * 16;

    float acc_o[2][8][4], acc_t[2][8][4];
    #pragma unroll
    for (int mt = 0; mt < 2; mt++)
        #pragma unroll
        for (int nt = 0; nt < 8; nt++)
            #pragma unroll
            for (int r = 0; r < 4; r++) { acc_o[mt][nt][r] = 0.f; acc_t[mt][nt][r] = 0.f; }

    const unsigned char* As[3] = { iy, ipred, iprev };
    const unsigned char* Bs[3] = { wpre + 3 * 65536, wpre + 6 * 65536, wpre + 7 * 65536 };
    stage_cp(sb, As[0], Bs[0], 0, tid, bm);
    stage_cp(sb + SM_BUF, As[0], Bs[0], 1, tid, bm);

    for (int s = 0; s < 6; s++) {
        if (s + 1 < 6) { CP_WAIT(1); } else { CP_WAIT(0); }
        __syncthreads();
        uint32_t base = sb + (s & 1) * SM_BUF;
        if (s < 2) mma_substage(acc_o, base, wm, wn, lrow, lc16);
        else       mma_substage(acc_t, base, wm, wn, lrow, lc16);
        __syncthreads();
        if (s + 2 < 6) {
            int ns = s + 2;
            stage_cp(sb + (s & 1) * SM_BUF, As[ns >> 1], Bs[ns >> 1], ns & 1, tid, bm);
        } else if (s == 4) {
            stage_cp_B(sb, wpre + 4 * 65536, 0, tid);   // Wg2 k0-63 -> buf0 B
        }
    }
    // buf A regions free: store silu(T1) hi/lo; stage Wg2 k64-127 -> buf1 B
    store_silu_tile(acc_t, bg1, sb, wm, wn, lane);
    stage_cp_B(sb + SM_BUF, wpre + 4 * 65536, 1, tid);
    CP_WAIT(0); __syncthreads();

    float acc_g[2][8][4];
    #pragma unroll
    for (int mt = 0; mt < 2; mt++)
        #pragma unroll
        for (int nt = 0; nt < 8; nt++)
            #pragma unroll
            for (int r = 0; r < 4; r++) acc_g[mt][nt][r] = 0.f;
    mma_substage(acc_g, sb, wm, wn, lrow, lc16);
    mma_substage(acc_g, sb + SM_BUF, wm, wn, lrow, lc16);

    #pragma unroll
    for (int mt = 0; mt < 2; mt++)
        #pragma unroll
        for (int half = 0; half < 2; half++) {
            int row = bm + wm + mt * 16 + (lane >> 2) + half * 8;
            if (row < M) {
                #pragma unroll
                for (int nt = 0; nt < 8; nt++) {
                    int col = wn + nt * 8 + 2 * (lane & 3);
                    float2 b1 = *(const float2*)&bo[col];
                    float2 b2 = *(const float2*)&bg2[col];
                    float o0 = acc_o[mt][nt][half * 2 + 0] + b1.x;
                    float o1 = acc_o[mt][nt][half * 2 + 1] + b1.y;
                    float gg0 = 1.f / (1.f + __expf(-(acc_g[mt][nt][half * 2 + 0] + b2.x)));
                    float gg1 = 1.f / (1.f + __expf(-(acc_g[mt][nt][half * 2 + 1] + b2.y)));
                    int idx = row * 128 + col;
                    float2 hp = *(const float2*)&h_prev[idx];
                    float c0 = hp.x + gg0 * o0;
                    float c1 = hp.y + gg1 * o1;
                    float h0 = bf16r(c0), h1 = bf16r(c1);
                    unsigned char* r = ihc + (size_t)row * IMG_ROW + col * 2;
                    *(uint32_t*)(r)       = pk(h0, h1);
                    *(uint32_t*)(r + 256) = pk(c0 - h0, c1 - h1);
                }
            }
        }
}

// ---------------- mlp: T2=silu(cat2@Wm1), out = hc + T2@Wm2 + bm2 ------------
__global__ __launch_bounds__(256, 1) void mlp_kernel(
    const unsigned char* __restrict__ ihc, const unsigned char* __restrict__ iprev,
    const unsigned char* __restrict__ wpre,
    const float* __restrict__ bm1, const float* __restrict__ bm2,
    float* __restrict__ out, int M)
{
    extern __shared__ char smem[];
    const uint32_t sb = smem_u32(smem);
    const int tid = threadIdx.x, wid = tid >> 5, lane = tid & 31;
    const int wm = (wid & 3) * 32, wn = (wid >> 2) * 64;
    const int bm = blockIdx.x * 128;
    const int lrow = lane & 15, lc16 = (lane >> 4) * 16;

    float acc_t[2][8][4];
    #pragma unroll
    for (int mt = 0; mt < 2; mt++)
        #pragma unroll
        for (int nt = 0; nt < 8; nt++)
            #pragma unroll
            for (int r = 0; r < 4; r++) acc_t[mt][nt][r] = 0.f;

    const unsigned char* As[2] = { ihc, iprev };
    const unsigned char* Bs[2] = { wpre + 8 * 65536, wpre + 9 * 65536 };
    stage_cp(sb, As[0], Bs[0], 0, tid, bm);
    stage_cp(sb + SM_BUF, As[0], Bs[0], 1, tid, bm);

    for (int s = 0; s < 4; s++) {
        if (s + 1 < 4) { CP_WAIT(1); } else { CP_WAIT(0); }
        __syncthreads();
        mma_substage(acc_t, sb + (s & 1) * SM_BUF, wm, wn, lrow, lc16);
        __syncthreads();
        if (s + 2 < 4) {
            int ns = s + 2;
            stage_cp(sb + (s & 1) * SM_BUF, As[ns >> 1], Bs[ns >> 1], ns & 1, tid, bm);
        } else if (s == 2) {
            stage_cp_B(sb, wpre + 5 * 65536, 0, tid);   // Wm2 k0-63 -> buf0 B
        }
    }
    store_silu_tile(acc_t, bm1, sb, wm, wn, lane);
    stage_cp_B(sb + SM_BUF, wpre + 5 * 65536, 1, tid);
    CP_WAIT(0); __syncthreads();

    float acc_m[2][8][4];
    #pragma unroll
    for (int mt = 0; mt < 2; mt++)
        #pragma unroll
        for (int nt = 0; nt < 8; nt++)
            #pragma unroll
            for (int r = 0; r < 4; r++) acc_m[mt][nt][r] = 0.f;
    mma_substage(acc_m, sb, wm, wn, lrow, lc16);
    mma_substage(acc_m, sb + SM_BUF, wm, wn, lrow, lc16);

    #pragma unroll
    for (int mt = 0; mt < 2; mt++)
        #pragma unroll
        for (int half = 0; half < 2; half++) {
            int row = bm + wm + mt * 16 + (lane >> 2) + half * 8;
            if (row < M) {
                #pragma unroll
                for (int nt = 0; nt < 8; nt++) {
                    int col = wn + nt * 8 + 2 * (lane & 3);
                    float2 b2 = *(const float2*)&bm2[col];
                    float m0 = acc_m[mt][nt][half * 2 + 0] + b2.x;
                    float m1 = acc_m[mt][nt][half * 2 + 1] + b2.y;
                    const unsigned char* r = ihc + (size_t)row * IMG_ROW + col * 2;
                    float2 hi = unpk(*(const uint32_t*)(r));
                    float2 lo = unpk(*(const uint32_t*)(r + 256));
                    float c0 = hi.x + lo.x, c1 = hi.y + lo.y;
                    *(float2*)&out[row * 128 + col] = make_float2(c0 + m0, c1 + m1);
                }
            }
        }
}

// ---------------- launch -----------------------------------------------------
extern "C" void kernel_launch(void* const* d_in, const int* in_sizes, int n_in,
                              void* d_out, int out_size) {
    const float* h_prev = (const float*)d_in[0];
    const float* h_pred = (const float*)d_in[1];
    const float* Wq  = (const float*)d_in[2];  const float* bq  = (const float*)d_in[3];
    const float* Wk  = (const float*)d_in[4];  const float* bk  = (const float*)d_in[5];
    const float* Wv  = (const float*)d_in[6];  const float* bv  = (const float*)d_in[7];
    const float* Wo  = (const float*)d_in[8];  const float* bo  = (const float*)d_in[9];
    const float* Wg1 = (const float*)d_in[10]; const float* bg1 = (const float*)d_in[11];
    const float* Wg2 = (const float*)d_in[12]; const float* bg2 = (const float*)d_in[13];
    const float* Wm1 = (const float*)d_in[14]; const float* bm1 = (const float*)d_in[15];
    const float* Wm2 = (const float*)d_in[16]; const float* bm2 = (const float*)d_in[17];
    const int* rows  = (const int*)d_in[18];
    const int* cols  = (const int*)d_in[19];
    const int N = in_sizes[0] / HID;
    const int E = in_sizes[18];
    float* out = (float*)d_out;

    float *q, *k, *v;
    int *cnt, *linc, *bsum, *bofs, *start, *cur, *ccol;
    unsigned char *ipred, *iprev, *iy, *ihc, *wpre;
    cudaGetSymbolAddress((void**)&q,   g_q);
    cudaGetSymbolAddress((void**)&k,   g_k);
    cudaGetSymbolAddress((void**)&v,   g_v);
    cudaGetSymbolAddress((void**)&ipred, g_ipred);
    cudaGetSymbolAddress((void**)&iprev, g_iprev);
    cudaGetSymbolAddress((void**)&iy,  g_iy);
    cudaGetSymbolAddress((void**)&ihc, g_ihc);
    cudaGetSymbolAddress((void**)&wpre, g_wpre);
    cudaGetSymbolAddress((void**)&cnt, g_cnt);
    cudaGetSymbolAddress((void**)&linc, g_linc);
    cudaGetSymbolAddress((void**)&bsum, g_bsum);
    cudaGetSymbolAddress((void**)&bofs, g_bofs);
    cudaGetSymbolAddress((void**)&start, g_start);
    cudaGetSymbolAddress((void**)&cur, g_cur);
    cudaGetSymbolAddress((void**)&ccol, g_ccol);

    cudaFuncSetAttribute(qkv_kernel,    cudaFuncAttributeMaxDynamicSharedMemorySize, SMEM_TOTAL);
    cudaFuncSetAttribute(gatehc_kernel, cudaFuncAttributeMaxDynamicSharedMemorySize, SMEM_TOTAL);
    cudaFuncSetAttribute(mlp_kernel,    cudaFuncAttributeMaxDynamicSharedMemorySize, SMEM_TOTAL);

    const int gb = (N + 127) / 128;
    const int nb = (N + 255) / 256;
    const float qscale = 0.17677669529663687f;   // 1/sqrt(32)

    // CSR build (deterministic multiblock scan)
    zero_int_kernel<<<(N + 255) / 256, 256>>>(cnt, N);
    hist_kernel<<<(E + 255) / 256, 256>>>(rows, cnt, E);
    scan1_kernel<<<nb, 256>>>(cnt, linc, bsum, N);
    scan2_kernel<<<1, 256>>>(bsum, bofs, nb);
    scan3_kernel<<<nb, 256>>>(bofs, linc, cnt, start, cur, N);
    scatter_kernel<<<(E + 255) / 256, 256>>>(rows, cols, cur, ccol, E);

    // input + weight image conversion
    hconv_kernel<<<dim3((N * 32 + 255) / 256, 2), 256>>>(h_pred, h_prev, ipred, iprev, N);
    WArg wa;
    wa.W[0] = Wq;  wa.W[1] = Wk;  wa.W[2] = Wv;  wa.W[3] = Wo;
    wa.W[4] = Wg2; wa.W[5] = Wm2; wa.W[6] = Wg1; wa.W[7] = Wg1;
    wa.W[8] = Wm1; wa.W[9] = Wm1;
    wconv_kernel<<<dim3(32, 10), 256>>>(wa, wpre);

    // q,k,v projections
    qkv_kernel<<<dim3(gb, 3), 256, SMEM_TOTAL>>>(ipred, iprev, wpre, bq, bk, bv,
                                                 q, k, v, N, qscale);

    // sparse multi-head attention (head-major) -> y image
    attn_kernel<<<(N + 7) / 8, 256>>>(q, k, v, ccol, start, cnt, iy, N);

    // fused gate + output projection + residual -> ihc image
    gatehc_kernel<<<gb, 256, SMEM_TOTAL>>>(iy, ipred, iprev, wpre, bo, bg1, bg2,
                                           h_prev, ihc, N);

    // fused MLP + final residual -> out
    mlp_kernel<<<gb, 256, SMEM_TOTAL>>>(ihc, iprev, wpre, bm1, bm2, out, N);
}